// round 12
// baseline (speedup 1.0000x reference)
#include <cuda_runtime.h>
#include <cstdint>

// Round 12: occupancy push. 256 threads / 8 warps per block; warp = (z-slab,
// ly-half) owning 2 m16-subtiles -> persistent regs halve (acc 16 + arow 24),
// __launch_bounds__(256,4) caps at 64 regs -> 8 warps/SMSP (was 5).
// MMA operands passed directly from arow[] (no lo/hi temps); k-step-major
// ordering retained. Weights rna->tf32 via prep kernel; activations raw fp32.

constexpr int N_TOTAL = 409600;
constexpr int W_FLOATS = 27 * 16 * 16;   // [tap][cout][ch]

__device__ float d_ws[W_FLOATS];

__device__ __forceinline__ float cvt_tf32(float v) {
    uint32_t o; asm("cvt.rna.tf32.f32 %0, %1;" : "=r"(o) : "f"(v));
    return __uint_as_float(o);
}

__device__ __forceinline__ uint32_t smem_u32(const void* p) {
    uint32_t a;
    asm("{ .reg .u64 t; cvta.to.shared.u64 t, %1; cvt.u32.u64 %0, t; }" : "=r"(a) : "l"(p));
    return a;
}

__device__ __forceinline__ void mma_tf32(float c[4], uint32_t a0, uint32_t a1,
                                         uint32_t a2, uint32_t a3,
                                         uint32_t b0, uint32_t b1) {
    asm volatile("mma.sync.aligned.m16n8k8.row.col.f32.tf32.tf32.f32 "
                 "{%0,%1,%2,%3}, {%4,%5,%6,%7}, {%8,%9}, {%0,%1,%2,%3};"
                 : "+f"(c[0]), "+f"(c[1]), "+f"(c[2]), "+f"(c[3])
                 : "r"(a0), "r"(a1), "r"(a2), "r"(a3), "r"(b0), "r"(b1));
}

// ---- prep: transpose + rna-round weights once: d_ws[tap][cout][ch] ----
__global__ void weight_prep_kernel(const float* __restrict__ wgt) {
    int i = blockIdx.x * 256 + threadIdx.x;
    if (i >= W_FLOATS) return;
    int tap = i >> 8;
    int rem = i & 255;
    int cout = rem >> 4, ch = rem & 15;
    d_ws[tap * 256 + cout * 16 + ch] = cvt_tf32(wgt[(cout * 16 + ch) * 27 + tap]);
}

__global__ __launch_bounds__(256, 4)
void conv3d_mma_kernel(const float* __restrict__ in,
                       const float* __restrict__ bias, float* __restrict__ out)
{
    __shared__ __align__(16) uint32_t halo[600 * 16];   // [row 600][ch 16]

    const int t = threadIdx.x;
    const int wid = t >> 5, lane = t & 31;
    const int r4 = lane >> 2, c4 = lane & 3;
    const int zslab = wid >> 1;        // 0..3
    const int half  = wid & 1;         // ly-half: rows 4*half .. 4*half+3

    // ---- decode block -> (batch, level, tile). 256-voxel tiles. ----
    int bid = blockIdx.x;
    int b = bid / 1600;
    int tl = bid - b * 1600;
    int R, nbase, lt;
    if (tl < 16)       { R = 16; nbase = 0;      lt = tl;       }
    else if (tl < 144) { R = 32; nbase = 4096;   lt = tl - 16;  }
    else if (tl < 576) { R = 48; nbase = 36864;  lt = tl - 144; }
    else               { R = 64; nbase = 147456; lt = tl - 576; }
    const int td = R >> 3;
    const int tx = lt % td; const int t2 = lt / td;
    const int ty = t2 % td; const int tz = t2 / td;
    const int x0 = tx << 3, y0 = ty << 3, z0 = tz << 2;

    // ---- stage halo via cp.async: incremental (hx,hy,hz), no div/mod ----
    const float* inb = in + ((size_t)b * N_TOTAL + nbase) * 16;
    {
        const int comp = t & 3;
        int row = t >> 2;                    // 0..63
        int hx = row % 10, hy0 = row / 10;
        int hy = hy0 % 10, hz = hy0 / 10;    // hy0 <= 6 -> hz = 0
        uint32_t dst = smem_u32(halo) + (uint32_t)(row * 16 + comp * 4) * 4u;
        const float* srcb = inb + comp * 4;
        int i = t;
        #pragma unroll
        for (int k = 0; k < 10; ++k) {
            if (i < 2400) {
                int gx = x0 + hx - 1, gy = y0 + hy - 1, gz = z0 + hz - 1;
                bool ok = (unsigned)gx < (unsigned)R && (unsigned)gy < (unsigned)R &&
                          (unsigned)gz < (unsigned)R;
                const float* src = ok ? srcb + (size_t)((gz * R + gy) * R + gx) * 16
                                      : inb;
                int sz = ok ? 16 : 0;
                asm volatile("cp.async.ca.shared.global [%0], [%1], 16, %2;"
                             :: "r"(dst), "l"(src), "r"(sz));
            }
            // advance 64 rows: 64 = 6*10 + 4
            hx += 4; hy += 6;
            if (hx >= 10) { hx -= 10; hy += 1; }
            if (hy >= 10) { hy -= 10; hz += 1; }
            dst += 64 * 16 * 4;
            i += 256;
        }
    }
    asm volatile("cp.async.commit_group;");
    asm volatile("cp.async.wait_group 0;" ::: "memory");
    __syncthreads();

    // ---- compute: warp = (zslab, half); 2 m16-subtiles; 6-row window ----
    float acc[2][2][4];
    #pragma unroll
    for (int s = 0; s < 2; ++s)
        #pragma unroll
        for (int n = 0; n < 2; ++n)
            #pragma unroll
            for (int k = 0; k < 4; ++k) acc[s][n][k] = 0.f;

    const uint4* hq = (const uint4*)halo + c4;                // + row*4
    const uint4* wq = (const uint4*)d_ws + r4 * 4 + c4;       // + tap*64
    const int rb0 = (zslab * 10 + 4 * half) * 10 + r4;        // dz=0, dx=0, j=0

    #pragma unroll 1
    for (int dx = 0; dx < 3; ++dx) {
        const uint4* hx0 = hq + (rb0 + dx) * 4;
        #pragma unroll
        for (int dz = 0; dz < 3; ++dz) {
            // 6-row window at (hz = zslab+dz, hy = 4*half.., hx = r4+dx)
            uint4 arow[6];
            #pragma unroll
            for (int j = 0; j < 6; ++j)
                arow[j] = hx0[(dz * 100 + 10 * j) * 4];

            #pragma unroll
            for (int dy = 0; dy < 3; ++dy) {
                const int tap = (dz * 3 + dy) * 3 + dx;
                uint4 bl = __ldg(wq + tap * 64);          // couts r4
                uint4 bh = __ldg(wq + tap * 64 + 32);     // couts r4+8
                // k-step 0 across both subtiles, both n-tiles
                #pragma unroll
                for (int s = 0; s < 2; ++s) {
                    mma_tf32(acc[s][0], arow[2*s+dy].x, arow[2*s+dy+1].x,
                                        arow[2*s+dy].y, arow[2*s+dy+1].y, bl.x, bl.y);
                    mma_tf32(acc[s][1], arow[2*s+dy].x, arow[2*s+dy+1].x,
                                        arow[2*s+dy].y, arow[2*s+dy+1].y, bh.x, bh.y);
                }
                // k-step 1
                #pragma unroll
                for (int s = 0; s < 2; ++s) {
                    mma_tf32(acc[s][0], arow[2*s+dy].z, arow[2*s+dy+1].z,
                                        arow[2*s+dy].w, arow[2*s+dy+1].w, bl.z, bl.w);
                    mma_tf32(acc[s][1], arow[2*s+dy].z, arow[2*s+dy+1].z,
                                        arow[2*s+dy].w, arow[2*s+dy+1].w, bh.z, bh.w);
                }
            }
        }
    }

    // ---- epilogue: +bias, store ----
    const int n0 = 2 * c4;
    const float bl0 = bias[n0],     bl1 = bias[n0 + 1];
    const float bh0 = bias[8 + n0], bh1 = bias[8 + n0 + 1];

    const int gz = z0 + zslab, gx = x0 + r4;
    #pragma unroll
    for (int s = 0; s < 2; ++s) {
        const int gy_lo = y0 + 4 * half + 2 * s, gy_hi = gy_lo + 1;
        float* olo = out + ((size_t)b * N_TOTAL + nbase +
                            (size_t)((gz * R + gy_lo) * R + gx)) * 16;
        float* ohi = out + ((size_t)b * N_TOTAL + nbase +
                            (size_t)((gz * R + gy_hi) * R + gx)) * 16;
        *(float2*)(olo + n0)     = make_float2(acc[s][0][0] + bl0, acc[s][0][1] + bl1);
        *(float2*)(olo + 8 + n0) = make_float2(acc[s][1][0] + bh0, acc[s][1][1] + bh1);
        *(float2*)(ohi + n0)     = make_float2(acc[s][0][2] + bl0, acc[s][0][3] + bl1);
        *(float2*)(ohi + 8 + n0) = make_float2(acc[s][1][2] + bh0, acc[s][1][3] + bh1);
    }
}

extern "C" void kernel_launch(void* const* d_in, const int* in_sizes, int n_in,
                              void* d_out, int out_size) {
    (void)in_sizes; (void)n_in; (void)out_size;
    const float* in  = (const float*)d_in[0];
    const float* w   = (const float*)d_in[1];
    const float* bs  = (const float*)d_in[2];
    float* out = (float*)d_out;

    weight_prep_kernel<<<27, 256>>>(w);
    conv3d_mma_kernel<<<6400, 256>>>(in, bs, out);
}

// round 13
// speedup vs baseline: 1.1027x; 1.1027x over previous
#include <cuda_runtime.h>
#include <cstdint>

// Round 13: revert to R11 tile/warp structure (best: 127.6us), test the
// register-pressure hypothesis for the ~1700 junk alu/fma slots per warp:
//  - __launch_bounds__(128, 4): 128-reg budget (was 96 @ 5 blocks) -> ptxas
//    scheduling slack, no register-churn MOVs.
//  - all 3 dy B-pairs (6 uint4) hoisted to the top of each dz stage.
// tile = 256 voxels (4z x 8y x 8x), 4 warps (one z-slab each), 4 blocks/SM.

constexpr int N_TOTAL = 409600;
constexpr int W_FLOATS = 27 * 16 * 16;   // [tap][cout][ch]

__device__ float d_ws[W_FLOATS];

__device__ __forceinline__ float cvt_tf32(float v) {
    uint32_t o; asm("cvt.rna.tf32.f32 %0, %1;" : "=r"(o) : "f"(v));
    return __uint_as_float(o);
}

__device__ __forceinline__ uint32_t smem_u32(const void* p) {
    uint32_t a;
    asm("{ .reg .u64 t; cvta.to.shared.u64 t, %1; cvt.u32.u64 %0, t; }" : "=r"(a) : "l"(p));
    return a;
}

__device__ __forceinline__ void mma_tf32(float c[4], uint32_t a0, uint32_t a1,
                                         uint32_t a2, uint32_t a3,
                                         uint32_t b0, uint32_t b1) {
    asm volatile("mma.sync.aligned.m16n8k8.row.col.f32.tf32.tf32.f32 "
                 "{%0,%1,%2,%3}, {%4,%5,%6,%7}, {%8,%9}, {%0,%1,%2,%3};"
                 : "+f"(c[0]), "+f"(c[1]), "+f"(c[2]), "+f"(c[3])
                 : "r"(a0), "r"(a1), "r"(a2), "r"(a3), "r"(b0), "r"(b1));
}

// ---- prep: transpose + rna-round weights once: d_ws[tap][cout][ch] ----
__global__ void weight_prep_kernel(const float* __restrict__ wgt) {
    int i = blockIdx.x * 256 + threadIdx.x;
    if (i >= W_FLOATS) return;
    int tap = i >> 8;
    int rem = i & 255;
    int cout = rem >> 4, ch = rem & 15;
    d_ws[tap * 256 + cout * 16 + ch] = cvt_tf32(wgt[(cout * 16 + ch) * 27 + tap]);
}

__global__ __launch_bounds__(128, 4)
void conv3d_mma_kernel(const float* __restrict__ in,
                       const float* __restrict__ bias, float* __restrict__ out)
{
    __shared__ __align__(16) uint32_t halo[600 * 16];   // [row 600][ch 16]

    const int t = threadIdx.x;
    const int wid = t >> 5, lane = t & 31;
    const int r4 = lane >> 2, c4 = lane & 3;

    // ---- decode block -> (batch, level, tile). 256-voxel tiles. ----
    int bid = blockIdx.x;
    int b = bid / 1600;
    int tl = bid - b * 1600;
    int R, nbase, lt;
    if (tl < 16)       { R = 16; nbase = 0;      lt = tl;       }
    else if (tl < 144) { R = 32; nbase = 4096;   lt = tl - 16;  }
    else if (tl < 576) { R = 48; nbase = 36864;  lt = tl - 144; }
    else               { R = 64; nbase = 147456; lt = tl - 576; }
    const int td = R >> 3;
    const int tx = lt % td; const int t2 = lt / td;
    const int ty = t2 % td; const int tz = t2 / td;
    const int x0 = tx << 3, y0 = ty << 3, z0 = tz << 2;

    // ---- stage halo via cp.async: incremental (hx,hy,hz), no div/mod ----
    const float* inb = in + ((size_t)b * N_TOTAL + nbase) * 16;
    {
        const int comp = t & 3;
        int row = t >> 2;                    // 0..31
        int hx = row % 10, hy = row / 10;
        int hz = 0;
        uint32_t dst = smem_u32(halo) + (uint32_t)(row * 16 + comp * 4) * 4u;
        const float* srcb = inb + comp * 4;
        int i = t;
        #pragma unroll
        for (int k = 0; k < 19; ++k) {
            if (i < 2400) {
                int gx = x0 + hx - 1, gy = y0 + hy - 1, gz = z0 + hz - 1;
                bool ok = (unsigned)gx < (unsigned)R && (unsigned)gy < (unsigned)R &&
                          (unsigned)gz < (unsigned)R;
                const float* src = ok ? srcb + (size_t)((gz * R + gy) * R + gx) * 16
                                      : inb;
                int sz = ok ? 16 : 0;
                asm volatile("cp.async.ca.shared.global [%0], [%1], 16, %2;"
                             :: "r"(dst), "l"(src), "r"(sz));
            }
            hx += 2; hy += 3;
            if (hx >= 10) { hx -= 10; hy += 1; }
            if (hy >= 10) { hy -= 10; hz += 1; }
            dst += 32 * 16 * 4;
            i += 128;
        }
    }
    asm volatile("cp.async.commit_group;");
    asm volatile("cp.async.wait_group 0;" ::: "memory");
    __syncthreads();

    // ---- compute: warp wid = z-slab; 10-row window; B hoisted per dz ----
    float acc[4][2][4];
    #pragma unroll
    for (int s = 0; s < 4; ++s)
        #pragma unroll
        for (int n = 0; n < 2; ++n)
            #pragma unroll
            for (int k = 0; k < 4; ++k) acc[s][n][k] = 0.f;

    const uint4* hq = (const uint4*)halo + c4;                    // + row*4
    const uint4* wq = (const uint4*)d_ws + r4 * 4 + c4;           // + tap*64
    const int rb0 = (wid * 10) * 10 + r4;                         // dz=0, dx=0

    #pragma unroll 1
    for (int dx = 0; dx < 3; ++dx) {
        const uint4* hx0 = hq + (rb0 + dx) * 4;
        #pragma unroll
        for (int dz = 0; dz < 3; ++dz) {
            // hoist all 3 dy weight pairs for this (dz, dx)
            uint4 bl[3], bh[3];
            #pragma unroll
            for (int dy = 0; dy < 3; ++dy) {
                const int tap = (dz * 3 + dy) * 3 + dx;
                bl[dy] = __ldg(wq + tap * 64);          // couts r4
                bh[dy] = __ldg(wq + tap * 64 + 32);     // couts r4+8
            }
            // 10-row window at (hz = wid+dz, hx = r4+dx)
            uint4 arow[10];
            #pragma unroll
            for (int j = 0; j < 10; ++j)
                arow[j] = hx0[(dz * 100 + 10 * j) * 4];

            #pragma unroll
            for (int dy = 0; dy < 3; ++dy) {
                // k-step 0 for all 8 accumulators...
                #pragma unroll
                for (int s = 0; s < 4; ++s) {
                    mma_tf32(acc[s][0], arow[2*s+dy].x, arow[2*s+dy+1].x,
                                        arow[2*s+dy].y, arow[2*s+dy+1].y,
                                        bl[dy].x, bl[dy].y);
                    mma_tf32(acc[s][1], arow[2*s+dy].x, arow[2*s+dy+1].x,
                                        arow[2*s+dy].y, arow[2*s+dy+1].y,
                                        bh[dy].x, bh[dy].y);
                }
                // ...then k-step 1
                #pragma unroll
                for (int s = 0; s < 4; ++s) {
                    mma_tf32(acc[s][0], arow[2*s+dy].z, arow[2*s+dy+1].z,
                                        arow[2*s+dy].w, arow[2*s+dy+1].w,
                                        bl[dy].z, bl[dy].w);
                    mma_tf32(acc[s][1], arow[2*s+dy].z, arow[2*s+dy+1].z,
                                        arow[2*s+dy].w, arow[2*s+dy+1].w,
                                        bh[dy].z, bh[dy].w);
                }
            }
        }
    }

    // ---- epilogue: +bias, store ----
    const int n0 = 2 * c4;
    const float bl0 = bias[n0],     bl1 = bias[n0 + 1];
    const float bh0 = bias[8 + n0], bh1 = bias[8 + n0 + 1];

    const int gz = z0 + wid, gx = x0 + r4;
    #pragma unroll
    for (int s = 0; s < 4; ++s) {
        const int gy_lo = y0 + 2 * s, gy_hi = gy_lo + 1;
        float* olo = out + ((size_t)b * N_TOTAL + nbase +
                            (size_t)((gz * R + gy_lo) * R + gx)) * 16;
        float* ohi = out + ((size_t)b * N_TOTAL + nbase +
                            (size_t)((gz * R + gy_hi) * R + gx)) * 16;
        *(float2*)(olo + n0)     = make_float2(acc[s][0][0] + bl0, acc[s][0][1] + bl1);
        *(float2*)(olo + 8 + n0) = make_float2(acc[s][1][0] + bh0, acc[s][1][1] + bh1);
        *(float2*)(ohi + n0)     = make_float2(acc[s][0][2] + bl0, acc[s][0][3] + bl1);
        *(float2*)(ohi + 8 + n0) = make_float2(acc[s][1][2] + bh0, acc[s][1][3] + bh1);
    }
}

extern "C" void kernel_launch(void* const* d_in, const int* in_sizes, int n_in,
                              void* d_out, int out_size) {
    (void)in_sizes; (void)n_in; (void)out_size;
    const float* in  = (const float*)d_in[0];
    const float* w   = (const float*)d_in[1];
    const float* bs  = (const float*)d_in[2];
    float* out = (float*)d_out;

    weight_prep_kernel<<<27, 256>>>(w);
    conv3d_mma_kernel<<<6400, 128>>>(in, bs, out);
}